// round 3
// baseline (speedup 1.0000x reference)
#include <cuda_runtime.h>
#include <cuda_bf16.h>
#include <math.h>

// Problem constants (fixed by the reference)
#define NN 20000
#define EE 640000
#define GG 128
#define H1 128
#define H2 128
#define RR 8
#define KAGG (RR * GG)   // 1024

// ---------------- scratch (device globals; device-code use only) -----------
__device__ float g_agg[(size_t)NN * KAGG]; // normalized aggregate  ~82MB
__device__ float g_h[NN * H1];
__device__ float g_q[NN * H2];
__device__ float g_k[NN * H2];
__device__ float g_v[NN * H2];
__device__ float g_e[EE];
__device__ float g_den[NN];
__device__ int   g_deg[NN];
__device__ int   g_cur[NN];
__device__ int   g_off[NN + 1];
__device__ int   g_eid[EE];

// ---------------- init ------------------------------------------------------
__global__ void zero_init_kernel() {
    int i = blockIdx.x * blockDim.x + threadIdx.x;
    if (i < NN) { g_deg[i] = 0; g_cur[i] = 0; g_den[i] = 0.f; }
}

// ---------------- CSR build -------------------------------------------------
__global__ void deg_kernel(const int* __restrict__ dst) {
    int e = blockIdx.x * blockDim.x + threadIdx.x;
    if (e < EE) atomicAdd(&g_deg[dst[e]], 1);
}

__global__ void scan_kernel() {
    __shared__ int sh[1024];
    __shared__ int carry_s;
    int tid = threadIdx.x;
    if (tid == 0) carry_s = 0;
    __syncthreads();
    for (int base = 0; base < NN; base += 1024) {
        int i = base + tid;
        int v = (i < NN) ? g_deg[i] : 0;
        sh[tid] = v;
        __syncthreads();
        #pragma unroll
        for (int o = 1; o < 1024; o <<= 1) {
            int t = (tid >= o) ? sh[tid - o] : 0;
            __syncthreads();
            sh[tid] += t;
            __syncthreads();
        }
        int carry = carry_s;
        if (i < NN) g_off[i + 1] = sh[tid] + carry;
        __syncthreads();
        if (tid == 1023) carry_s = carry + sh[1023];
        __syncthreads();
    }
    if (tid == 0) g_off[0] = 0;
}

__global__ void fill_kernel(const int* __restrict__ dst) {
    int e = blockIdx.x * blockDim.x + threadIdx.x;
    if (e >= EE) return;
    int d = dst[e];
    int p = atomicAdd(&g_cur[d], 1);
    g_eid[g_off[d] + p] = e;
}

// ---------------- RGCN aggregation: warp per node, no atomics ---------------
__global__ void agg_kernel(const int* __restrict__ src,
                           const int* __restrict__ et,
                           const float* __restrict__ x) {
    int node = blockIdx.x * 8 + (threadIdx.x >> 5);
    if (node >= NN) return;
    int lane = threadIdx.x & 31;
    int beg = g_off[node], end = g_off[node + 1];

    float4 a0 = {0,0,0,0}, a1 = {0,0,0,0}, a2 = {0,0,0,0}, a3 = {0,0,0,0};
    float4 a4 = {0,0,0,0}, a5 = {0,0,0,0}, a6 = {0,0,0,0}, a7 = {0,0,0,0};
    int c0=0,c1=0,c2=0,c3=0,c4=0,c5=0,c6=0,c7=0;

    for (int i = beg; i < end; i++) {
        int e = __ldg(&g_eid[i]);
        int s = __ldg(&src[e]);
        int r = __ldg(&et[e]);
        float4 xv = *(const float4*)&x[(size_t)s * GG + lane * 4];
        switch (r) {
            case 0: a0.x+=xv.x; a0.y+=xv.y; a0.z+=xv.z; a0.w+=xv.w; c0++; break;
            case 1: a1.x+=xv.x; a1.y+=xv.y; a1.z+=xv.z; a1.w+=xv.w; c1++; break;
            case 2: a2.x+=xv.x; a2.y+=xv.y; a2.z+=xv.z; a2.w+=xv.w; c2++; break;
            case 3: a3.x+=xv.x; a3.y+=xv.y; a3.z+=xv.z; a3.w+=xv.w; c3++; break;
            case 4: a4.x+=xv.x; a4.y+=xv.y; a4.z+=xv.z; a4.w+=xv.w; c4++; break;
            case 5: a5.x+=xv.x; a5.y+=xv.y; a5.z+=xv.z; a5.w+=xv.w; c5++; break;
            case 6: a6.x+=xv.x; a6.y+=xv.y; a6.z+=xv.z; a6.w+=xv.w; c6++; break;
            default: a7.x+=xv.x; a7.y+=xv.y; a7.z+=xv.z; a7.w+=xv.w; c7++; break;
        }
    }

    float* base = g_agg + (size_t)node * KAGG + lane * 4;
    #define STORE_R(R_, A_, C_) { \
        float inv = 1.0f / fmaxf((float)C_, 1.0f); \
        float4 o; o.x = A_.x * inv; o.y = A_.y * inv; \
        o.z = A_.z * inv; o.w = A_.w * inv; \
        *(float4*)(base + (R_) * GG) = o; }
    STORE_R(0, a0, c0) STORE_R(1, a1, c1) STORE_R(2, a2, c2) STORE_R(3, a3, c3)
    STORE_R(4, a4, c4) STORE_R(5, a5, c5) STORE_R(6, a6, c6) STORE_R(7, a7, c7)
    #undef STORE_R
}

// ---------------- 128x128x16 GEMM core --------------------------------------
// C[M,128] tile per block; 256 threads, 8x8 microtile each.
__device__ __forceinline__ void mm_seg(const float* __restrict__ A, int lda, int K,
                                       const float* __restrict__ B,
                                       float (*As)[128], float (*Bs)[128],
                                       int row0, int M, float acc[8][8]) {
    int tid = threadIdx.x;
    int tx = tid & 15, ty = tid >> 4;
    for (int k0 = 0; k0 < K; k0 += 16) {
        #pragma unroll
        for (int i = 0; i < 2; i++) {
            int idx = tid + i * 256;        // 0..511
            int r = idx >> 2;               // row 0..127
            int kc = (idx & 3) * 4;         // 0,4,8,12
            int gr = row0 + r;
            float4 v = make_float4(0.f, 0.f, 0.f, 0.f);
            if (gr < M) v = *(const float4*)&A[(size_t)gr * lda + k0 + kc];
            As[kc + 0][r] = v.x; As[kc + 1][r] = v.y;
            As[kc + 2][r] = v.z; As[kc + 3][r] = v.w;
        }
        #pragma unroll
        for (int i = 0; i < 2; i++) {
            int idx = tid + i * 256;        // 0..511
            int kk = idx >> 5;              // 0..15
            int c = (idx & 31) * 4;
            *(float4*)&Bs[kk][c] = *(const float4*)&B[(size_t)(k0 + kk) * 128 + c];
        }
        __syncthreads();
        #pragma unroll
        for (int kk = 0; kk < 16; kk++) {
            float4 p0 = *(float4*)&As[kk][ty * 8];
            float4 p1 = *(float4*)&As[kk][ty * 8 + 4];
            float4 q0 = *(float4*)&Bs[kk][tx * 8];
            float4 q1 = *(float4*)&Bs[kk][tx * 8 + 4];
            float av[8] = {p0.x,p0.y,p0.z,p0.w,p1.x,p1.y,p1.z,p1.w};
            float bv[8] = {q0.x,q0.y,q0.z,q0.w,q1.x,q1.y,q1.z,q1.w};
            #pragma unroll
            for (int i = 0; i < 8; i++)
                #pragma unroll
                for (int j = 0; j < 8; j++) acc[i][j] += av[i] * bv[j];
        }
        __syncthreads();
    }
}

__device__ __forceinline__ void mm_epilogue(float* __restrict__ C,
                                            const float* __restrict__ bias,
                                            int row0, int M, float acc[8][8],
                                            int do_relu) {
    int tid = threadIdx.x;
    int tx = tid & 15, ty = tid >> 4;
    #pragma unroll
    for (int i = 0; i < 8; i++) {
        int gr = row0 + ty * 8 + i;
        if (gr >= M) continue;
        #pragma unroll
        for (int j = 0; j < 8; j++) {
            int c = tx * 8 + j;
            float vv = acc[i][j] + bias[c];
            if (do_relu) vv = fmaxf(vv, 0.f);
            C[(size_t)gr * 128 + c] = vv;
        }
    }
}

// h = relu(agg @ W_stack + x @ root + bias)
__global__ void __launch_bounds__(256)
gemm_h_kernel(const float* __restrict__ x,
              const float* __restrict__ W,      // [1024,128]
              const float* __restrict__ root,   // [128,128]
              const float* __restrict__ bias) {
    __shared__ float As[16][128];
    __shared__ float Bs[16][128];
    float acc[8][8];
    #pragma unroll
    for (int i = 0; i < 8; i++)
        #pragma unroll
        for (int j = 0; j < 8; j++) acc[i][j] = 0.f;
    int row0 = blockIdx.x * 128;
    mm_seg(g_agg, KAGG, KAGG, W, As, Bs, row0, NN, acc);
    mm_seg(x, GG, GG, root, As, Bs, row0, NN, acc);
    mm_epilogue(g_h, bias, row0, NN, acc, 1);
}

// q/k/v/skip in one launch: blockIdx.y selects the matrix
__global__ void __launch_bounds__(256)
gemm_qkvs_kernel(const float* __restrict__ Wq, const float* __restrict__ bq,
                 const float* __restrict__ Wk, const float* __restrict__ bk,
                 const float* __restrict__ Wv, const float* __restrict__ bv,
                 const float* __restrict__ Ws, const float* __restrict__ bs,
                 float* __restrict__ out) {
    const float* B; const float* bias; float* C;
    switch (blockIdx.y) {
        case 0:  B = Wq; bias = bq; C = g_q; break;
        case 1:  B = Wk; bias = bk; C = g_k; break;
        case 2:  B = Wv; bias = bv; C = g_v; break;
        default: B = Ws; bias = bs; C = out; break;
    }
    __shared__ float As[16][128];
    __shared__ float Bs[16][128];
    float acc[8][8];
    #pragma unroll
    for (int i = 0; i < 8; i++)
        #pragma unroll
        for (int j = 0; j < 8; j++) acc[i][j] = 0.f;
    int row0 = blockIdx.x * 128;
    mm_seg(g_h, H1, H1, B, As, Bs, row0, NN, acc);
    mm_epilogue(C, bias, row0, NN, acc, 0);
}

// ---------------- fused score + exp + denominator ---------------------------
// No max-subtraction: |score| <= |q||k|/sqrt(128) ~ 6 << 88, exp is safe, and
// alpha = e/sum(e) is mathematically identical to the max-shifted form.
__global__ void score_exp_kernel(const int* __restrict__ src,
                                 const int* __restrict__ dst) {
    int e = blockIdx.x * 8 + (threadIdx.x >> 5);
    if (e >= EE) return;
    int lane = threadIdx.x & 31;
    int s = src[e], d = dst[e];
    float4 qv = *(const float4*)&g_q[(size_t)d * H2 + lane * 4];
    float4 kv = *(const float4*)&g_k[(size_t)s * H2 + lane * 4];
    float acc = qv.x * kv.x + qv.y * kv.y + qv.z * kv.z + qv.w * kv.w;
    #pragma unroll
    for (int o = 16; o; o >>= 1) acc += __shfl_xor_sync(0xFFFFFFFFu, acc, o);
    if (lane == 0) {
        float ex = __expf(acc * 0.08838834764831845f);  // 1/sqrt(128)
        g_e[e] = ex;
        atomicAdd(&g_den[d], ex);
    }
}

// ---------------- weighted V scatter ----------------------------------------
__global__ void scatter_v_kernel(const int* __restrict__ src,
                                 const int* __restrict__ dst,
                                 float* __restrict__ out) {
    int e = blockIdx.x * 8 + (threadIdx.x >> 5);
    if (e >= EE) return;
    int lane = threadIdx.x & 31;
    int s = src[e], d = dst[e];
    float alpha = g_e[e] / fmaxf(g_den[d], 1e-16f);
    float4 vv = *(const float4*)&g_v[(size_t)s * H2 + lane * 4];
    float* od = out + (size_t)d * H2 + lane * 4;
    atomicAdd(od + 0, alpha * vv.x);
    atomicAdd(od + 1, alpha * vv.y);
    atomicAdd(od + 2, alpha * vv.z);
    atomicAdd(od + 3, alpha * vv.w);
}

// ---------------- final relu in place ---------------------------------------
__global__ void relu_kernel(float* __restrict__ out, int n) {
    int i = blockIdx.x * blockDim.x + threadIdx.x;
    if (i < n) out[i] = fmaxf(out[i], 0.f);
}

// ---------------------------------------------------------------------------
extern "C" void kernel_launch(void* const* d_in, const int* in_sizes, int n_in,
                              void* d_out, int out_size) {
    const float* x        = (const float*)d_in[0];
    const int* edge_index = (const int*)d_in[1];   // [2, E]: src then dst
    const int* etype      = (const int*)d_in[2];
    const float* rgcn_w   = (const float*)d_in[3]; // [R, G, H1] == [1024,128]
    const float* rgcn_root= (const float*)d_in[4];
    const float* rgcn_b   = (const float*)d_in[5];
    const float* Wq = (const float*)d_in[6];  const float* bq = (const float*)d_in[7];
    const float* Wk = (const float*)d_in[8];  const float* bk = (const float*)d_in[9];
    const float* Wv = (const float*)d_in[10]; const float* bv = (const float*)d_in[11];
    const float* Ws = (const float*)d_in[12]; const float* bs = (const float*)d_in[13];
    float* out = (float*)d_out;

    const int* src = edge_index;
    const int* dst = edge_index + EE;

    // init + CSR build
    zero_init_kernel<<<(NN + 255) / 256, 256>>>();
    deg_kernel<<<(EE + 255) / 256, 256>>>(dst);
    scan_kernel<<<1, 1024>>>();
    fill_kernel<<<(EE + 255) / 256, 256>>>(dst);

    // RGCN aggregation (atomic-free, normalized)
    agg_kernel<<<(NN + 7) / 8, 256>>>(src, etype, x);

    // h = relu(agg @ W + x @ root + b)
    gemm_h_kernel<<<(NN + 127) / 128, 256>>>(x, rgcn_w, rgcn_root, rgcn_b);

    // q, k, v, skip(->out) in one launch
    dim3 gq((NN + 127) / 128, 4);
    gemm_qkvs_kernel<<<gq, 256>>>(Wq, bq, Wk, bk, Wv, bv, Ws, bs, out);

    // attention: fused score+exp+den
    score_exp_kernel<<<(EE + 7) / 8, 256>>>(src, dst);

    // alpha * v scatter onto skip
    scatter_v_kernel<<<(EE + 7) / 8, 256>>>(src, dst, out);

    // final relu
    relu_kernel<<<(NN * H2 + 255) / 256, 256>>>(out, NN * H2);
}